// round 1
// baseline (speedup 1.0000x reference)
#include <cuda_runtime.h>
#include <math.h>

#define Wd 14
#define Hd 14
#define Bd 64
#define Cd 256
#define NEG 64
#define HWBC (14*14*64*256)

// Scratch (static device globals; no allocation)
__device__ float g_zt[HWBC];            // [h][w][b][c]
__device__ float g_ct[HWBC];            // [h][w][b][c]
__device__ float g_Y[12*14*64*256];     // max rows (k=1: Hp=12) x 256

// ---------------------------------------------------------------- init
__global__ void init_out(float* out) { if (threadIdx.x == 0) out[0] = 0.f; }

// ------------------------------------------------------------ transpose
// zt[h][w][b][c] = z[b][c][h][w]; same for c.
__global__ void transpose_kernel(const float* __restrict__ z,
                                 const float* __restrict__ c) {
    int idx = blockIdx.x * blockDim.x + threadIdx.x;
    if (idx >= HWBC) return;
    int ch = idx & 255;
    int b  = (idx >> 8) & 63;
    int hw = idx >> 14;
    int w  = hw % 14;
    int h  = hw / 14;
    int src = ((b * Cd + ch) * Hd + h) * Wd + w;
    g_zt[idx] = z[src];
    g_ct[idx] = c[src];
}

// ---------------------------------------------------------------- GEMM
// Y[row][o] = sum_c A[row][c] * Wk[o][c],  A = g_zt + aoff (row-major, C fast)
// BM=64, BN=64, BK=16, 256 threads, 4x4 microtile.
__global__ __launch_bounds__(256) void gemm_kernel(const float* __restrict__ Wk,
                                                   int aoff, int rows) {
    __shared__ __align__(16) float sA[16][68];
    __shared__ __align__(16) float sB[16][68];
    int tid  = threadIdx.x;
    int row0 = blockIdx.x * 64;
    int o0   = blockIdx.y * 64;
    int lrow = tid >> 2;          // 0..63
    int lc4  = (tid & 3) * 4;     // 0,4,8,12
    int tx   = tid & 15;
    int ty   = tid >> 4;

    const float* __restrict__ Arow = g_zt + aoff + (size_t)(row0 + lrow) * Cd;
    const float* __restrict__ Brow = Wk + (size_t)(o0 + lrow) * Cd;

    float acc[4][4] = {};

    for (int kc = 0; kc < Cd; kc += 16) {
        float4 av = *(const float4*)(Arow + kc + lc4);
        float4 bv = *(const float4*)(Brow + kc + lc4);
        __syncthreads();
        sA[lc4 + 0][lrow] = av.x; sA[lc4 + 1][lrow] = av.y;
        sA[lc4 + 2][lrow] = av.z; sA[lc4 + 3][lrow] = av.w;
        sB[lc4 + 0][lrow] = bv.x; sB[lc4 + 1][lrow] = bv.y;
        sB[lc4 + 2][lrow] = bv.z; sB[lc4 + 3][lrow] = bv.w;
        __syncthreads();
#pragma unroll
        for (int kk = 0; kk < 16; kk++) {
            float4 a = *(const float4*)&sA[kk][ty * 4];
            float4 b = *(const float4*)&sB[kk][tx * 4];
            float ar[4] = {a.x, a.y, a.z, a.w};
            float br[4] = {b.x, b.y, b.z, b.w};
#pragma unroll
            for (int i = 0; i < 4; i++)
#pragma unroll
                for (int j = 0; j < 4; j++)
                    acc[i][j] = fmaf(ar[i], br[j], acc[i][j]);
        }
    }
#pragma unroll
    for (int i = 0; i < 4; i++) {
        float4 o = make_float4(acc[i][0], acc[i][1], acc[i][2], acc[i][3]);
        *(float4*)(g_Y + (size_t)(row0 + ty * 4 + i) * Cd + o0 + tx * 4) = o;
    }
}

// ------------------------------------------------------- dot + softmax
// One warp per row. 65 targets (main + 64 negs), processed 8 per pass
// (one quad of lanes per target; each lane covers 64 of 256 components).
__global__ __launch_bounds__(256) void dot_kernel(const int* __restrict__ negidx,
                                                  float* __restrict__ out,
                                                  int rows, float invw) {
    __shared__ __align__(16) float s_ctx[8][256];
    __shared__ int   s_tgt[8][72];
    __shared__ float s_logit[8][72];

    int warp = threadIdx.x >> 5;
    int lane = threadIdx.x & 31;
    int r = blockIdx.x * 8 + warp;
    if (r >= rows) return;

    // stage ctx row (coalesced from transposed layout)
    const float4* __restrict__ ctr = (const float4*)(g_ct + (size_t)r * Cd);
    float4* sc4 = (float4*)s_ctx[warp];
    sc4[lane]      = ctr[lane];
    sc4[lane + 32] = ctr[lane + 32];

    // target list: slot 0 = self (main), 1..64 = negatives, 65..71 pad
    if (lane == 0) s_tgt[warp][0] = r;
    s_tgt[warp][1 + lane]  = negidx[(size_t)r * NEG + lane];
    s_tgt[warp][33 + lane] = negidx[(size_t)r * NEG + 32 + lane];
    if (lane < 7) s_tgt[warp][65 + lane] = 0;
    __syncwarp();

    int q  = lane >> 2;   // quad id: which target in this pass
    int ql = lane & 3;    // position within quad

#pragma unroll 1
    for (int p = 0; p < 9; p++) {
        int slot = p * 8 + q;
        int j = s_tgt[warp][slot];
        const float4* __restrict__ Yr = (const float4*)(g_Y + (size_t)j * Cd);
        float acc = 0.f;
#pragma unroll
        for (int i = 0; i < 16; i++) {
            float4 yv = Yr[i * 4 + ql];
            float4 cv = sc4[i * 4 + ql];
            acc = fmaf(yv.x, cv.x, acc);
            acc = fmaf(yv.y, cv.y, acc);
            acc = fmaf(yv.z, cv.z, acc);
            acc = fmaf(yv.w, cv.w, acc);
        }
        acc += __shfl_xor_sync(0xffffffffu, acc, 1);
        acc += __shfl_xor_sync(0xffffffffu, acc, 2);
        if (ql == 0) s_logit[warp][slot] = (slot < 65) ? acc : -INFINITY;
    }
    __syncwarp();

    float v0 = s_logit[warp][lane];
    float v1 = s_logit[warp][lane + 32];
    float v2 = (lane < 8) ? s_logit[warp][lane + 64] : -INFINITY;
    float m = fmaxf(v0, fmaxf(v1, v2));
#pragma unroll
    for (int o = 16; o; o >>= 1) m = fmaxf(m, __shfl_xor_sync(0xffffffffu, m, o));
    float s = expf(v0 - m) + expf(v1 - m) + expf(v2 - m);
#pragma unroll
    for (int o = 16; o; o >>= 1) s += __shfl_xor_sync(0xffffffffu, s, o);

    if (lane == 0) {
        float l0 = s_logit[warp][0];
        float p0 = expf(l0 - m) / s;
        atomicAdd(out, -logf(p0 + 1e-11f) * invw);
    }
}

// ---------------------------------------------------------------- host
extern "C" void kernel_launch(void* const* d_in, const int* in_sizes, int n_in,
                              void* d_out, int out_size) {
    const float* z  = (const float*)d_in[0];
    const float* c  = (const float*)d_in[1];
    const float* Wk = (const float*)d_in[2];
    const int* negs[3] = {(const int*)d_in[3], (const int*)d_in[4],
                          (const int*)d_in[5]};
    float* out = (float*)d_out;

    init_out<<<1, 32>>>(out);
    transpose_kernel<<<HWBC / 256, 256>>>(z, c);

    for (int k = 1; k <= 3; k++) {
        int Hp = Hd - (k + 1);
        int rows = Hp * Wd * Bd;              // multiple of 64 and of 8
        int aoff = (k + 1) * Wd * Bd * Cd;    // skip first (k+1) h-planes
        dim3 ggrid(rows / 64, 4);
        gemm_kernel<<<ggrid, 256>>>(Wk + (size_t)(k - 1) * Cd * Cd, aoff, rows);
        float invw = 1.0f / (3.0f * (float)rows);
        dot_kernel<<<rows / 8, 256>>>(negs[k - 1], out, rows, invw);
    }
}